// round 6
// baseline (speedup 1.0000x reference)
#include <cuda_runtime.h>
#include <cuda_bf16.h>
#include <cstdint>

// ---------------------------------------------------------------------------
// GE2E loss, N_SPK=1024, N_UTT=32, D=128.
// bf16 HMMA GEMM of ehat[32768x128] x chat^T[128x1024]; w*log2e folded into
// ehat, b*log2e into accum init -> accums are log2(exp(logit)). Fused ex2
// row-sum; own-column fixed at the end via ecorr = exp(ol) - exp(l_full).
// ---------------------------------------------------------------------------

#define NS 1024
#define NU 32
#define DD 128
#define NROWS (NS * NU)          // 32768
#define EPS 1e-8f
#define L2E 1.4426950408889634f

__device__ __align__(16) __nv_bfloat16 g_ehatb[NROWS * DD];   // 8 MB (pre-scaled w*log2e)
__device__ __align__(16) __nv_bfloat16 g_chatb[NS * DD];      // 256 KB
__device__ __align__(16) float2 g_own[NROWS];                 // (ol, ecorr)
__device__ __align__(16) float g_partial[NROWS / 128];        // 256

// ---------------- helpers ---------------------------------------------------
__device__ __forceinline__ uint32_t smem_u32(const void* p) {
    uint32_t a;
    asm("{ .reg .u64 t; cvta.to.shared.u64 t, %1; cvt.u32.u64 %0, t; }"
        : "=r"(a) : "l"(p));
    return a;
}
#define CP_ASYNC16(dst_u32, src_ptr) \
    asm volatile("cp.async.ca.shared.global [%0], [%1], 16;" :: "r"(dst_u32), "l"(src_ptr))
#define CP_COMMIT() asm volatile("cp.async.commit_group;")
#define CP_WAIT(n)  asm volatile("cp.async.wait_group %0;" :: "n"(n))

__device__ __forceinline__ void ldsm_x4(uint32_t addr, uint32_t& r0, uint32_t& r1,
                                        uint32_t& r2, uint32_t& r3) {
    asm volatile("ldmatrix.sync.aligned.m8n8.x4.shared.b16 {%0,%1,%2,%3}, [%4];"
                 : "=r"(r0), "=r"(r1), "=r"(r2), "=r"(r3) : "r"(addr));
}
__device__ __forceinline__ void mma16816(float* d, const uint32_t* a,
                                         uint32_t b0, uint32_t b1) {
    asm volatile(
        "mma.sync.aligned.m16n8k16.row.col.f32.bf16.bf16.f32 "
        "{%0,%1,%2,%3}, {%4,%5,%6,%7}, {%8,%9}, {%0,%1,%2,%3};"
        : "+f"(d[0]), "+f"(d[1]), "+f"(d[2]), "+f"(d[3])
        : "r"(a[0]), "r"(a[1]), "r"(a[2]), "r"(a[3]), "r"(b0), "r"(b1));
}

// stage a 128x128 bf16 tile (row-major 256B rows, contiguous 32KB) into smem
// with XOR-16B swizzle: chunk (r,c) -> r*256 + ((c ^ (r&7)) << 4).
// 2048 16B chunks, 512 threads x 4.
__device__ __forceinline__ void stage_tile(uint32_t sdst, const char* src, int tid) {
#pragma unroll
    for (int i = 0; i < 4; i++) {
        uint32_t q = (uint32_t)tid + i * 512u;       // 0..2047
        uint32_t r = q >> 4, c = q & 15u;
        uint32_t sw = r * 256u + ((c ^ (r & 7u)) << 4);
        CP_ASYNC16(sdst + sw, src + (size_t)q * 16);
    }
}

// ===========================================================================
// Kernel 1: prep. block = 1 speaker, 128 threads. Shuffle-free per-utterance
// reductions via padded smem transpose (129-float rows -> conflict-free).
// ===========================================================================
__global__ void __launch_bounds__(128) k_prep(const float* __restrict__ emb,
                                              const float* __restrict__ wp,
                                              const float* __restrict__ bp) {
    __shared__ float es[NU][129];
    __shared__ float Sar[DD];
    __shared__ float4 sred[4][32];
    __shared__ float dotw[4][32];
    __shared__ float e2w[4][32];
    __shared__ float sc[NU];

    const int n = blockIdx.x, t = threadIdx.x;
    const int wq = t >> 5, lane = t & 31;
    const float4* base = (const float4*)(emb + (size_t)n * NU * DD);

    float4 e4[8];
    float4 s4 = make_float4(0.f, 0.f, 0.f, 0.f);
#pragma unroll
    for (int i = 0; i < 8; i++) {
        int m = wq + 4 * i;
        e4[i] = base[m * 32 + lane];
        s4.x += e4[i].x; s4.y += e4[i].y; s4.z += e4[i].z; s4.w += e4[i].w;
        es[m][lane * 4 + 0] = e4[i].x;
        es[m][lane * 4 + 1] = e4[i].y;
        es[m][lane * 4 + 2] = e4[i].z;
        es[m][lane * 4 + 3] = e4[i].w;
    }
    sred[wq][lane] = s4;
    __syncthreads();
    float4 S0 = sred[0][lane], S1 = sred[1][lane], S2_ = sred[2][lane], S3 = sred[3][lane];
    float4 S4;
    S4.x = S0.x + S1.x + S2_.x + S3.x;
    S4.y = S0.y + S1.y + S2_.y + S3.y;
    S4.z = S0.z + S1.z + S2_.z + S3.z;
    S4.w = S0.w + S1.w + S2_.w + S3.w;
    if (wq == 0) {
        Sar[lane * 4 + 0] = S4.x; Sar[lane * 4 + 1] = S4.y;
        Sar[lane * 4 + 2] = S4.z; Sar[lane * 4 + 3] = S4.w;
    }
    float s2 = S4.x * S4.x + S4.y * S4.y + S4.z * S4.z + S4.w * S4.w;
#pragma unroll
    for (int o = 16; o > 0; o >>= 1) s2 += __shfl_xor_sync(0xffffffffu, s2, o);
    const float S2 = s2;
    __syncthreads();

    // phase 2: warp wq reduces d in [32wq, 32wq+32) for utterance lane
    float dta = 0.f, dtb = 0.f, eea = 0.f, eeb = 0.f;
#pragma unroll
    for (int j = 0; j < 32; j += 2) {
        int d0 = wq * 32 + j;
        float ev0 = es[lane][d0],     ev1 = es[lane][d0 + 1];
        dta = fmaf(ev0, Sar[d0], dta); dtb = fmaf(ev1, Sar[d0 + 1], dtb);
        eea = fmaf(ev0, ev0, eea);     eeb = fmaf(ev1, ev1, eeb);
    }
    dotw[wq][lane] = dta + dtb;
    e2w[wq][lane] = eea + eeb;
    __syncthreads();

    const float w = *wp, b = *bp;
    const float wl2e = w * L2E;
    const float cn = fmaxf(sqrtf(S2) * (1.f / NU), EPS);

    if (wq == 0) {
        float dt = dotw[0][lane] + dotw[1][lane] + dotw[2][lane] + dotw[3][lane];
        float ee = e2w[0][lane] + e2w[1][lane] + e2w[2][lane] + e2w[3][lane];
        float en = fmaxf(sqrtf(ee), EPS);
        float d2 = fmaxf(S2 - 2.f * dt + ee, 0.f);
        float cen = fmaxf(sqrtf(d2) * (1.f / (NU - 1)), EPS);
        float sim_ex = ((dt - ee) * (1.f / (NU - 1))) / (en * cen);
        float sim_fl = (dt * (1.f / NU)) / (en * cn);
        float ol = w * sim_ex + b;
        float lf = w * sim_fl + b;
        g_own[n * NU + lane] = make_float2(ol, __expf(ol) - __expf(lf));
        sc[lane] = wl2e / en;
    } else if (wq == 1) {
        float inv = (1.f / NU) / cn;
        __nv_bfloat162* dst = (__nv_bfloat162*)(g_chatb + n * DD + lane * 4);
        dst[0] = __nv_bfloat162(__float2bfloat16(S4.x * inv), __float2bfloat16(S4.y * inv));
        dst[1] = __nv_bfloat162(__float2bfloat16(S4.z * inv), __float2bfloat16(S4.w * inv));
    }
    __syncthreads();

#pragma unroll
    for (int i = 0; i < 8; i++) {
        int m = wq + 4 * i;
        float s = sc[m];
        __nv_bfloat162* dst = (__nv_bfloat162*)(g_ehatb + ((size_t)n * NU + m) * DD + lane * 4);
        dst[0] = __nv_bfloat162(__float2bfloat16(e4[i].x * s), __float2bfloat16(e4[i].y * s));
        dst[1] = __nv_bfloat162(__float2bfloat16(e4[i].z * s), __float2bfloat16(e4[i].w * s));
    }
}

// ===========================================================================
// Kernel 2: HMMA GEMM 128 rows/CTA x 1024 cols, fused ex2 row-sum + loss.
// 512 thr = 16 warps (8m x 2n), warp tile 16x64. A frags hoisted to regs
// (loaded once); per n-pair: 8 LDSM -> 16 HMMA -> 8 ex2 (pipes interleave).
// 8 col-chunks of 128, double-buffered cp.async.
// ===========================================================================
#define SMEM_GEMM (1024 + 3 * 32768)

__global__ void __launch_bounds__(512, 1) k_gemm(const float* __restrict__ bp) {
    extern __shared__ char smc[];
    __shared__ float rowsum[128][2];
    __shared__ float redp[16];

    uint32_t sbase = (smem_u32(smc) + 1023u) & ~1023u;
    const uint32_t sA = sbase, sB0 = sbase + 32768u, sB1 = sB0 + 32768u;

    const int tid = threadIdx.x, wq = tid >> 5, lane = tid & 31;
    const int wm = wq >> 1, wn = wq & 1;
    const int rb = blockIdx.x * 128;

    stage_tile(sA, (const char*)g_ehatb + (size_t)rb * 256, tid);
    stage_tile(sB0, (const char*)g_chatb, tid);
    CP_COMMIT();
    stage_tile(sB1, (const char*)g_chatb + 32768, tid);
    CP_COMMIT();

    const float bl2e = (*bp) * L2E;

    // A fragment addresses (16-row warp tile)
    const uint32_t hxA = (uint32_t)(lane >> 4);
    const uint32_t rA = (uint32_t)(wm * 16 + (lane & 15));
    const uint32_t rxA = rA & 7u;
    const uint32_t baseA = sA + rA * 256u;
    // B fragment addresses
    uint32_t offB[4];
#pragma unroll
    for (int p = 0; p < 4; p++) {
        uint32_t nB = (uint32_t)(wn * 64 + p * 16 + (lane & 7) + ((lane >> 4) << 3));
        offB[p] = nB * 256u;
    }
    const uint32_t kxB = (uint32_t)((lane >> 3) & 1);
    const uint32_t rxB = (uint32_t)(lane & 7);

    // wait for A + B0; hoist all A fragments into registers (A is static)
    CP_WAIT(1);
    __syncthreads();
    uint32_t a[8][4];
#pragma unroll
    for (int k = 0; k < 8; k++) {
        uint32_t ca = (((uint32_t)(2 * k) + hxA) ^ rxA) << 4;
        ldsm_x4(baseA + ca, a[k][0], a[k][1], a[k][2], a[k][3]);
    }

    float racc[2] = {0.f, 0.f};

    for (int ci = 0; ci < 8; ci++) {
        if (ci > 0) {
            if (ci < 7) { CP_WAIT(1); } else { CP_WAIT(0); }
            __syncthreads();
        }
        const uint32_t sB = (ci & 1) ? sB1 : sB0;

#pragma unroll
        for (int ntp = 0; ntp < 4; ntp++) {
            float d0[4] = {bl2e, bl2e, bl2e, bl2e};
            float d1[4] = {bl2e, bl2e, bl2e, bl2e};
#pragma unroll
            for (int k = 0; k < 8; k++) {
                uint32_t b0, b1, b2, b3;
                uint32_t cb = (((uint32_t)(2 * k) + kxB) ^ rxB) << 4;
                ldsm_x4(sB + offB[ntp] + cb, b0, b1, b2, b3);
                mma16816(d0, a[k], b0, b1);
                mma16816(d1, a[k], b2, b3);
            }
#pragma unroll
            for (int e = 0; e < 4; e++) {
                float ev0, ev1;
                asm("ex2.approx.ftz.f32 %0, %1;" : "=f"(ev0) : "f"(d0[e]));
                asm("ex2.approx.ftz.f32 %0, %1;" : "=f"(ev1) : "f"(d1[e]));
                racc[e >> 1] += ev0 + ev1;
            }
        }

        __syncthreads();               // all reads of buf (ci&1) done
        if (ci + 2 < 8) {
            stage_tile((ci & 1) ? sB1 : sB0,
                       (const char*)g_chatb + (size_t)(ci + 2) * 32768, tid);
            CP_COMMIT();
        }
    }

    // reduce the 4 lanes sharing each row-subgroup
#pragma unroll
    for (int j = 0; j < 2; j++) {
        racc[j] += __shfl_xor_sync(0xffffffffu, racc[j], 1);
        racc[j] += __shfl_xor_sync(0xffffffffu, racc[j], 2);
    }
    if ((lane & 3) == 0) {
        int g = lane >> 2;
#pragma unroll
        for (int j = 0; j < 2; j++)
            rowsum[wm * 16 + j * 8 + g][wn] = racc[j];
    }
    __syncthreads();

    float val = 0.f;
    if (tid < 128) {
        float Ssum = rowsum[tid][0] + rowsum[tid][1];
        float2 oc = g_own[rb + tid];
        val = __logf(Ssum + oc.y) - oc.x;
    }
#pragma unroll
    for (int o = 16; o > 0; o >>= 1) val += __shfl_xor_sync(0xffffffffu, val, o);
    if (lane == 0) redp[wq] = val;
    __syncthreads();
    if (tid == 0) {
        float tsum = 0.f;
#pragma unroll
        for (int i = 0; i < 16; i++) tsum += redp[i];
        g_partial[blockIdx.x] = tsum;
    }
}

// ===========================================================================
// Kernel 3: reduce 256 partials -> mean
// ===========================================================================
__global__ void __launch_bounds__(256) k_reduce(float* __restrict__ out) {
    const int t = threadIdx.x;
    float v = g_partial[t];
#pragma unroll
    for (int o = 16; o > 0; o >>= 1) v += __shfl_xor_sync(0xffffffffu, v, o);
    __shared__ float red[8];
    if ((t & 31) == 0) red[t >> 5] = v;
    __syncthreads();
    if (t == 0) {
        float x = 0.f;
#pragma unroll
        for (int i = 0; i < 8; i++) x += red[i];
        out[0] = x * (1.f / NROWS);
    }
}

// ===========================================================================
extern "C" void kernel_launch(void* const* d_in, const int* in_sizes, int n_in,
                              void* d_out, int out_size) {
    const float* emb = (const float*)d_in[0];
    const float* w   = (const float*)d_in[1];
    const float* b   = (const float*)d_in[2];

    cudaFuncSetAttribute(k_gemm, cudaFuncAttributeMaxDynamicSharedMemorySize,
                         SMEM_GEMM);

    k_prep<<<NS, 128>>>(emb, w, b);
    k_gemm<<<NROWS / 128, 512, SMEM_GEMM>>>(b);
    k_reduce<<<1, 256>>>((float*)d_out);
}

// round 7
// speedup vs baseline: 1.1714x; 1.1714x over previous
#include <cuda_runtime.h>
#include <cuda_bf16.h>
#include <cstdint>

// ---------------------------------------------------------------------------
// GE2E loss, N_SPK=1024, N_UTT=32, D=128.
// bf16 HMMA GEMM of ehat[32768x128] x chat^T[128x1024]; w*log2e folded into
// ehat, b*log2e into accum init -> accums are log2(exp(logit)). Fused ex2
// row-sum; own-column fixed at the end via ecorr = exp(ol) - exp(l_full).
// k_gemm: 128 rows x 256 cols per CTA, B smem-resident, zero-sync mainloop.
// ---------------------------------------------------------------------------

#define NS 1024
#define NU 32
#define DD 128
#define NROWS (NS * NU)          // 32768
#define EPS 1e-8f
#define L2E 1.4426950408889634f

__device__ __align__(16) __nv_bfloat16 g_ehatb[NROWS * DD];   // 8 MB (pre-scaled w*log2e)
__device__ __align__(16) __nv_bfloat16 g_chatb[NS * DD];      // 256 KB
__device__ __align__(16) float2 g_own[NROWS];                 // (ol, ecorr)
__device__ __align__(16) float g_rowpart[4 * NROWS];          // 512 KB col-split partials
__device__ __align__(16) float g_partial[64];

// ---------------- helpers ---------------------------------------------------
__device__ __forceinline__ uint32_t smem_u32(const void* p) {
    uint32_t a;
    asm("{ .reg .u64 t; cvta.to.shared.u64 t, %1; cvt.u32.u64 %0, t; }"
        : "=r"(a) : "l"(p));
    return a;
}
#define CP_ASYNC16(dst_u32, src_ptr) \
    asm volatile("cp.async.ca.shared.global [%0], [%1], 16;" :: "r"(dst_u32), "l"(src_ptr))
#define CP_COMMIT() asm volatile("cp.async.commit_group;")
#define CP_WAIT(n)  asm volatile("cp.async.wait_group %0;" :: "n"(n))

__device__ __forceinline__ void ldsm_x4(uint32_t addr, uint32_t& r0, uint32_t& r1,
                                        uint32_t& r2, uint32_t& r3) {
    asm volatile("ldmatrix.sync.aligned.m8n8.x4.shared.b16 {%0,%1,%2,%3}, [%4];"
                 : "=r"(r0), "=r"(r1), "=r"(r2), "=r"(r3) : "r"(addr));
}
__device__ __forceinline__ void mma16816(float* d, const uint32_t* a,
                                         uint32_t b0, uint32_t b1) {
    asm volatile(
        "mma.sync.aligned.m16n8k16.row.col.f32.bf16.bf16.f32 "
        "{%0,%1,%2,%3}, {%4,%5,%6,%7}, {%8,%9}, {%0,%1,%2,%3};"
        : "+f"(d[0]), "+f"(d[1]), "+f"(d[2]), "+f"(d[3])
        : "r"(a[0]), "r"(a[1]), "r"(a[2]), "r"(a[3]), "r"(b0), "r"(b1));
}

// ===========================================================================
// Kernel 1: prep. block = 1 speaker, 128 threads (R6 version).
// ===========================================================================
__global__ void __launch_bounds__(128) k_prep(const float* __restrict__ emb,
                                              const float* __restrict__ wp,
                                              const float* __restrict__ bp) {
    __shared__ float es[NU][129];
    __shared__ float Sar[DD];
    __shared__ float4 sred[4][32];
    __shared__ float dotw[4][32];
    __shared__ float e2w[4][32];
    __shared__ float sc[NU];

    const int n = blockIdx.x, t = threadIdx.x;
    const int wq = t >> 5, lane = t & 31;
    const float4* base = (const float4*)(emb + (size_t)n * NU * DD);

    float4 e4[8];
    float4 s4 = make_float4(0.f, 0.f, 0.f, 0.f);
#pragma unroll
    for (int i = 0; i < 8; i++) {
        int m = wq + 4 * i;
        e4[i] = base[m * 32 + lane];
        s4.x += e4[i].x; s4.y += e4[i].y; s4.z += e4[i].z; s4.w += e4[i].w;
        es[m][lane * 4 + 0] = e4[i].x;
        es[m][lane * 4 + 1] = e4[i].y;
        es[m][lane * 4 + 2] = e4[i].z;
        es[m][lane * 4 + 3] = e4[i].w;
    }
    sred[wq][lane] = s4;
    __syncthreads();
    float4 S0 = sred[0][lane], S1 = sred[1][lane], S2_ = sred[2][lane], S3 = sred[3][lane];
    float4 S4;
    S4.x = S0.x + S1.x + S2_.x + S3.x;
    S4.y = S0.y + S1.y + S2_.y + S3.y;
    S4.z = S0.z + S1.z + S2_.z + S3.z;
    S4.w = S0.w + S1.w + S2_.w + S3.w;
    if (wq == 0) {
        Sar[lane * 4 + 0] = S4.x; Sar[lane * 4 + 1] = S4.y;
        Sar[lane * 4 + 2] = S4.z; Sar[lane * 4 + 3] = S4.w;
    }
    float s2 = S4.x * S4.x + S4.y * S4.y + S4.z * S4.z + S4.w * S4.w;
#pragma unroll
    for (int o = 16; o > 0; o >>= 1) s2 += __shfl_xor_sync(0xffffffffu, s2, o);
    const float S2 = s2;
    __syncthreads();

    float dta = 0.f, dtb = 0.f, eea = 0.f, eeb = 0.f;
#pragma unroll
    for (int j = 0; j < 32; j += 2) {
        int d0 = wq * 32 + j;
        float ev0 = es[lane][d0],     ev1 = es[lane][d0 + 1];
        dta = fmaf(ev0, Sar[d0], dta); dtb = fmaf(ev1, Sar[d0 + 1], dtb);
        eea = fmaf(ev0, ev0, eea);     eeb = fmaf(ev1, ev1, eeb);
    }
    dotw[wq][lane] = dta + dtb;
    e2w[wq][lane] = eea + eeb;
    __syncthreads();

    const float w = *wp, b = *bp;
    const float wl2e = w * L2E;
    const float cn = fmaxf(sqrtf(S2) * (1.f / NU), EPS);

    if (wq == 0) {
        float dt = dotw[0][lane] + dotw[1][lane] + dotw[2][lane] + dotw[3][lane];
        float ee = e2w[0][lane] + e2w[1][lane] + e2w[2][lane] + e2w[3][lane];
        float en = fmaxf(sqrtf(ee), EPS);
        float d2 = fmaxf(S2 - 2.f * dt + ee, 0.f);
        float cen = fmaxf(sqrtf(d2) * (1.f / (NU - 1)), EPS);
        float sim_ex = ((dt - ee) * (1.f / (NU - 1))) / (en * cen);
        float sim_fl = (dt * (1.f / NU)) / (en * cn);
        float ol = w * sim_ex + b;
        float lf = w * sim_fl + b;
        g_own[n * NU + lane] = make_float2(ol, __expf(ol) - __expf(lf));
        sc[lane] = wl2e / en;
    } else if (wq == 1) {
        float inv = (1.f / NU) / cn;
        __nv_bfloat162* dst = (__nv_bfloat162*)(g_chatb + n * DD + lane * 4);
        dst[0] = __nv_bfloat162(__float2bfloat16(S4.x * inv), __float2bfloat16(S4.y * inv));
        dst[1] = __nv_bfloat162(__float2bfloat16(S4.z * inv), __float2bfloat16(S4.w * inv));
    }
    __syncthreads();

#pragma unroll
    for (int i = 0; i < 8; i++) {
        int m = wq + 4 * i;
        float s = sc[m];
        __nv_bfloat162* dst = (__nv_bfloat162*)(g_ehatb + ((size_t)n * NU + m) * DD + lane * 4);
        dst[0] = __nv_bfloat162(__float2bfloat16(e4[i].x * s), __float2bfloat16(e4[i].y * s));
        dst[1] = __nv_bfloat162(__float2bfloat16(e4[i].z * s), __float2bfloat16(e4[i].w * s));
    }
}

// ===========================================================================
// Kernel 2: HMMA GEMM, 128 rows x 256 cols per CTA, B smem-resident.
// 256 thr = 8 m-warps (16 rows each). ONE sync after staging; mainloop is
// sync-free: per 16-col subtile: 8 LDSM -> 16 HMMA -> 8 ex2 -> 8 FADD.
// grid = 1024 (256 rowblocks x 4 colblocks). occ 2.
// ===========================================================================
#define SMEM_GEMM (1024 + 32768 + 65536)

__global__ void __launch_bounds__(256, 2) k_gemm(const float* __restrict__ bp) {
    extern __shared__ char smc[];
    uint32_t sbase = (smem_u32(smc) + 1023u) & ~1023u;
    const uint32_t sA = sbase, sB = sbase + 32768u;

    const int tid = threadIdx.x, wq = tid >> 5, lane = tid & 31;
    const int rbi = blockIdx.x >> 2, cbi = blockIdx.x & 3;
    const int rb = rbi * 128;

    // stage A (32 KB) + B (64 KB), one group, one wait, one sync
    {
        const char* srcA = (const char*)g_ehatb + (size_t)rb * 256;
#pragma unroll
        for (int i = 0; i < 8; i++) {
            uint32_t q = (uint32_t)tid + i * 256u;       // 0..2047
            uint32_t r = q >> 4, c = q & 15u;
            uint32_t sw = r * 256u + ((c ^ (r & 7u)) << 4);
            CP_ASYNC16(sA + sw, srcA + (size_t)q * 16);
        }
        const char* srcB = (const char*)g_chatb + (size_t)cbi * 65536;
#pragma unroll
        for (int i = 0; i < 16; i++) {
            uint32_t q = (uint32_t)tid + i * 256u;       // 0..4095
            uint32_t r = q >> 4, c = q & 15u;
            uint32_t sw = r * 256u + ((c ^ (r & 7u)) << 4);
            CP_ASYNC16(sB + sw, srcB + (size_t)q * 16);
        }
        CP_COMMIT();
    }

    const float bl2e = (*bp) * L2E;

    // A fragment addresses (16-row warp tile)
    const uint32_t hxA = (uint32_t)(lane >> 4);
    const uint32_t rA = (uint32_t)(wq * 16 + (lane & 15));
    const uint32_t rxA = rA & 7u;
    const uint32_t baseA = sA + rA * 256u;
    // B fragment base: subtile p adds p*16 rows = p*4096 bytes
    const uint32_t nB0 = (uint32_t)((lane & 7) + ((lane >> 4) << 3));
    const uint32_t baseB = sB + nB0 * 256u;
    const uint32_t kxB = (uint32_t)((lane >> 3) & 1);
    const uint32_t rxB = (uint32_t)(lane & 7);

    CP_WAIT(0);
    __syncthreads();                 // ONLY block-wide sync in this kernel

    // hoist all A fragments (A reused for all 256 cols)
    uint32_t a[8][4];
#pragma unroll
    for (int k = 0; k < 8; k++) {
        uint32_t ca = (((uint32_t)(2 * k) + hxA) ^ rxA) << 4;
        ldsm_x4(baseA + ca, a[k][0], a[k][1], a[k][2], a[k][3]);
    }

    float racc[2] = {0.f, 0.f};

#pragma unroll 2
    for (int ntp = 0; ntp < 16; ntp++) {
        uint32_t bb = baseB + (uint32_t)ntp * 4096u;
        float d0[4] = {bl2e, bl2e, bl2e, bl2e};
        float d1[4] = {bl2e, bl2e, bl2e, bl2e};
#pragma unroll
        for (int k = 0; k < 8; k++) {
            uint32_t b0, b1, b2, b3;
            uint32_t cb = (((uint32_t)(2 * k) + kxB) ^ rxB) << 4;
            ldsm_x4(bb + cb, b0, b1, b2, b3);
            mma16816(d0, a[k], b0, b1);
            mma16816(d1, a[k], b2, b3);
        }
#pragma unroll
        for (int e = 0; e < 4; e++) {
            float ev0, ev1;
            asm("ex2.approx.ftz.f32 %0, %1;" : "=f"(ev0) : "f"(d0[e]));
            asm("ex2.approx.ftz.f32 %0, %1;" : "=f"(ev1) : "f"(d1[e]));
            racc[e >> 1] += ev0 + ev1;
        }
    }

    // fold lanes sharing a row (lane bits 0,1), store per-CTA row partials
#pragma unroll
    for (int j = 0; j < 2; j++) {
        racc[j] += __shfl_xor_sync(0xffffffffu, racc[j], 1);
        racc[j] += __shfl_xor_sync(0xffffffffu, racc[j], 2);
    }
    if ((lane & 3) == 0) {
        int g = lane >> 2;
#pragma unroll
        for (int j = 0; j < 2; j++)
            g_rowpart[cbi * NROWS + rb + wq * 16 + j * 8 + g] = racc[j];
    }
}

// ===========================================================================
// Kernel 3: per-row loss from 4 col-partials + own correction; 64 partials.
// ===========================================================================
__global__ void __launch_bounds__(512) k_final() {
    const int row = blockIdx.x * 512 + threadIdx.x;
    const int t = threadIdx.x, lane = t & 31;
    float2 oc = g_own[row];
    float S = g_rowpart[row] + g_rowpart[NROWS + row]
            + g_rowpart[2 * NROWS + row] + g_rowpart[3 * NROWS + row];
    float val = __logf(S + oc.y) - oc.x;
#pragma unroll
    for (int o = 16; o > 0; o >>= 1) val += __shfl_xor_sync(0xffffffffu, val, o);
    __shared__ float red[16];
    if (lane == 0) red[t >> 5] = val;
    __syncthreads();
    if (t == 0) {
        float x = 0.f;
#pragma unroll
        for (int i = 0; i < 16; i++) x += red[i];
        g_partial[blockIdx.x] = x;
    }
}

__global__ void __launch_bounds__(64) k_reduce(float* __restrict__ out) {
    const int t = threadIdx.x;
    float v = g_partial[t];
#pragma unroll
    for (int o = 16; o > 0; o >>= 1) v += __shfl_xor_sync(0xffffffffu, v, o);
    __shared__ float red[2];
    if ((t & 31) == 0) red[t >> 5] = v;
    __syncthreads();
    if (t == 0) out[0] = (red[0] + red[1]) * (1.f / NROWS);
}

// ===========================================================================
extern "C" void kernel_launch(void* const* d_in, const int* in_sizes, int n_in,
                              void* d_out, int out_size) {
    const float* emb = (const float*)d_in[0];
    const float* w   = (const float*)d_in[1];
    const float* b   = (const float*)d_in[2];

    cudaFuncSetAttribute(k_gemm, cudaFuncAttributeMaxDynamicSharedMemorySize,
                         SMEM_GEMM);

    k_prep<<<NS, 128>>>(emb, w, b);
    k_gemm<<<1024, 256, SMEM_GEMM>>>(b);
    k_final<<<64, 512>>>();
    k_reduce<<<1, 64>>>((float*)d_out);
}